// round 7
// baseline (speedup 1.0000x reference)
#include <cuda_runtime.h>
#include <cuda_bf16.h>

// SEIR Euler integration — pipelined checkpoint scheme, checkpoints in-place.
//
// Phase 2 (the 536 MB store stream) is pinned at ~5.6 TB/s (68% DRAM) across
// configs -> write-bandwidth ceiling. The remaining recoverable time is the
// ~10 us serial phase-1 prologue. Fix: split phase 1 into NSTAGE time-stages
// and overlap stage s+1's chain with stage s's store kernel via a fork-join
// multi-stream graph (event edges; capture-legal).
//
//   default: P1_0 -> P1_1 -> P1_2 -> P1_3 ----------------- (join)
//   side:        \-> P2_0 ---> P2_1 ---> P2_2 ---> P2_3 --/
//
// Only P1_0 (~2 us) is exposed.

#define CHUNK  32
#define NSTAGE 4

__device__ __forceinline__ float4 seir_step(float4 v, float bh, float gh, float sh)
{
    const float S = v.x, E = v.y, I = v.z, R = v.w;
    const float p = bh * S;
    float4 r;
    r.x = __fmaf_rn(-p, I, S);
    r.y = __fmaf_rn( p, I, __fmaf_rn(-sh, E, E));
    r.z = __fmaf_rn( sh, E, __fmaf_rn(-gh, I, I));
    r.w = __fmaf_rn( gh, I, R);
    return r;
}

// ---- Phase 1 stage: advance [n_start, n_end), writing CHUNK-boundary
//      checkpoints (and the hand-off state at n_end) into out[]. ----
__global__ void __launch_bounds__(128) seir_ckpt_stage(
    const float* __restrict__ initial,
    const float* __restrict__ beta,
    const float* __restrict__ gamma,
    const float* __restrict__ sigma,
    float4* __restrict__ out,
    int B, int t, int n_start, int n_end)
{
    const int b = blockIdx.x * blockDim.x + threadIdx.x;
    if (b >= B) return;

    const float step = 0.5f;
    const float bh = beta[0]  * step;
    const float gh = gamma[0] * step;
    const float sh = sigma[0] * step;

    float4 v;
    if (n_start == 0) {
        v = make_float4(initial[0 * B + b], initial[1 * B + b],
                        initial[2 * B + b], initial[3 * B + b]);
    } else {
        v = out[(size_t)n_start * B + b];   // hand-off from previous stage
    }

    int c = n_start;
    while (c < n_end && c < t) {
        out[(size_t)c * B + b] = v;         // checkpoint at step c (L2 for P2)
        const int steps = min(CHUNK, t - c);
        #pragma unroll 8
        for (int j = 0; j < steps; ++j)
            v = seir_step(v, bh, gh, sh);
        c += CHUNK;
    }
    if (c == n_end && c < t)
        out[(size_t)c * B + b] = v;         // hand-off for next stage
}

// ---- Phase 2 stage: fill the CHUNK-1 interior steps of chunks [k0, k1). ----
__global__ void __launch_bounds__(256) seir_store_stage(
    const float* __restrict__ beta,
    const float* __restrict__ gamma,
    const float* __restrict__ sigma,
    float4* __restrict__ out,
    int B, int t, int k0, int k1)
{
    const int tid = blockIdx.x * blockDim.x + threadIdx.x;
    const int k  = k0 + tid / B;
    const int bb = tid - (k - k0) * B;
    if (k >= k1 || bb >= B) return;

    const int n0 = k * CHUNK;
    if (n0 >= t) return;

    const float step = 0.5f;
    const float bh = beta[0]  * step;
    const float gh = gamma[0] * step;
    const float sh = sigma[0] * step;

    size_t idx = (size_t)n0 * B + bb;
    float4 v = out[idx];                    // chunk-start checkpoint (L2 hot)

    const int nlast = min(n0 + CHUNK, t);
    if (nlast == n0 + CHUNK) {
        #pragma unroll
        for (int j = 1; j < CHUNK; ++j) {
            v = seir_step(v, bh, gh, sh);
            idx += B;
            __stcs(&out[idx], v);
        }
    } else {
        for (int n = n0 + 1; n < nlast; ++n) {
            v = seir_step(v, bh, gh, sh);
            idx += B;
            __stcs(&out[idx], v);
        }
    }
}

extern "C" void kernel_launch(void* const* d_in, const int* in_sizes, int n_in,
                              void* d_out, int out_size)
{
    const float* initial = (const float*)d_in[0];   // 4*B elements
    const float* beta    = (const float*)d_in[1];
    const float* gamma   = (const float*)d_in[2];
    const float* sigma   = (const float*)d_in[3];

    const int B = in_sizes[0] / 4;
    const int t = (B > 0) ? (out_size / (4 * B)) : 0;
    if (B <= 0 || t <= 0) return;

    // Side stream + events, created once on the first (pre-capture) call.
    // Non-blocking stream avoids legacy-default implicit sync; events are
    // timing-disabled (graph-edge only). No device memory is allocated here.
    static cudaStream_t side = nullptr;
    static cudaEvent_t  ev_p1[NSTAGE];
    static cudaEvent_t  ev_join = nullptr;
    if (side == nullptr) {
        cudaStreamCreateWithFlags(&side, cudaStreamNonBlocking);
        for (int s = 0; s < NSTAGE; ++s)
            cudaEventCreateWithFlags(&ev_p1[s], cudaEventDisableTiming);
        cudaEventCreateWithFlags(&ev_join, cudaEventDisableTiming);
    }

    const int nchunks = (t + CHUNK - 1) / CHUNK;
    const int cps     = (nchunks + NSTAGE - 1) / NSTAGE;   // chunks per stage

    const int p1_grid = (B + 127) / 128;

    for (int s = 0; s < NSTAGE; ++s) {
        const int k0 = s * cps;
        const int k1 = min(nchunks, (s + 1) * cps);
        if (k0 >= k1) break;

        const int n_start = k0 * CHUNK;
        const int n_end   = k1 * CHUNK;

        // P1 stage s on the (captured) default stream
        seir_ckpt_stage<<<p1_grid, 128>>>(initial, beta, gamma, sigma,
                                          (float4*)d_out, B, t, n_start, n_end);
        cudaEventRecord(ev_p1[s], 0);
        cudaStreamWaitEvent(side, ev_p1[s], 0);

        // P2 stage s on the side stream (overlaps P1 stage s+1)
        const long long total = (long long)(k1 - k0) * B;
        const int grid = (int)((total + 255) / 256);
        seir_store_stage<<<grid, 256, 0, side>>>(beta, gamma, sigma,
                                                 (float4*)d_out, B, t, k0, k1);
    }

    // Join side stream back into the default stream before capture ends.
    cudaEventRecord(ev_join, side);
    cudaStreamWaitEvent(0, ev_join, 0);
}

// round 8
// speedup vs baseline: 1.0669x; 1.0669x over previous
#include <cuda_runtime.h>
#include <cuda_bf16.h>

// SEIR Euler integration — two-phase checkpoint scheme, checkpoints in-place.
//
// Phase 1: B threads run the serial chain, writing every CHUNK-boundary state
//          directly to its final out[] slot (default policy -> L2-resident).
// Phase 2: persistent exact-fit grid; each thread grid-strides over chunk work
//          items, advancing TWO independent chunk chains interleaved (ILP 2)
//          and stream-storing the 31 interior steps of each.
//
// Round-7 lesson: splitting P2 into sub-wave stages collapses write BW
// (3.3 TB/s vs 5.6 monolithic). Keep P2 monolithic; raise its BW via
// persistent grid (no wave tail) + dual-chain store ILP.

#define CHUNK 32
#define NSM   148
#define P2_BLOCK 256
#define P2_GRID (NSM * 8)

__device__ __forceinline__ float4 seir_step(float4 v, float bh, float gh, float sh)
{
    const float S = v.x, E = v.y, I = v.z, R = v.w;
    const float p = bh * S;
    float4 r;
    r.x = __fmaf_rn(-p, I, S);
    r.y = __fmaf_rn( p, I, __fmaf_rn(-sh, E, E));
    r.z = __fmaf_rn( sh, E, __fmaf_rn(-gh, I, I));
    r.w = __fmaf_rn( gh, I, R);
    return r;
}

// ---- Phase 1: serial chain, checkpoints straight into out[] ----
__global__ void __launch_bounds__(128) seir_ckpt_kernel(
    const float* __restrict__ initial,
    const float* __restrict__ beta,
    const float* __restrict__ gamma,
    const float* __restrict__ sigma,
    float4* __restrict__ out,
    int B, int t)
{
    const int b = blockIdx.x * blockDim.x + threadIdx.x;
    if (b >= B) return;

    const float step = 0.5f;
    const float bh = beta[0]  * step;
    const float gh = gamma[0] * step;
    const float sh = sigma[0] * step;

    float4 v = make_float4(initial[0 * B + b], initial[1 * B + b],
                           initial[2 * B + b], initial[3 * B + b]);
    out[b] = v;  // step 0 (final slot, default policy -> L2)

    const int nchunks = (t + CHUNK - 1) / CHUNK;
    for (int c = 1; c < nchunks; ++c) {
        #pragma unroll 8
        for (int j = 0; j < CHUNK; ++j)
            v = seir_step(v, bh, gh, sh);
        out[(size_t)c * CHUNK * B + b] = v;  // step c*CHUNK
    }
}

// Store the CHUNK-1 interior steps of one chunk (scalar path / tail).
__device__ __forceinline__ void fill_chunk(
    float4* __restrict__ out, long long w, int B, int t,
    float bh, float gh, float sh)
{
    const int c  = (int)(w / B);
    const int bb = (int)(w - (long long)c * B);
    const int n0 = c * CHUNK;
    size_t idx = (size_t)n0 * B + bb;
    float4 v = out[idx];
    const int nlast = min(n0 + CHUNK, t);
    for (int n = n0 + 1; n < nlast; ++n) {
        v = seir_step(v, bh, gh, sh);
        idx += B;
        __stcs(&out[idx], v);
    }
}

// ---- Phase 2: persistent grid, dual-chain ILP ----
__global__ void __launch_bounds__(P2_BLOCK) seir_store_kernel(
    const float* __restrict__ beta,
    const float* __restrict__ gamma,
    const float* __restrict__ sigma,
    float4* __restrict__ out,
    int B, int t, long long total)
{
    const long long tid    = blockIdx.x * (long long)blockDim.x + threadIdx.x;
    const long long stride = (long long)gridDim.x * blockDim.x;

    const float step = 0.5f;
    const float bh = beta[0]  * step;
    const float gh = gamma[0] * step;
    const float sh = sigma[0] * step;

    for (long long w = tid; w < total; w += 2 * stride) {
        const long long w2 = w + stride;

        const int c1  = (int)(w / B);
        const int b1  = (int)(w - (long long)c1 * B);
        const int n01 = c1 * CHUNK;

        if (w2 < total && n01 + CHUNK <= t) {
            const int c2  = (int)(w2 / B);
            const int b2  = (int)(w2 - (long long)c2 * B);
            const int n02 = c2 * CHUNK;
            if (n02 + CHUNK <= t) {
                size_t i1 = (size_t)n01 * B + b1;
                size_t i2 = (size_t)n02 * B + b2;
                float4 v1 = out[i1];
                float4 v2 = out[i2];
                #pragma unroll
                for (int j = 1; j < CHUNK; ++j) {
                    v1 = seir_step(v1, bh, gh, sh);
                    v2 = seir_step(v2, bh, gh, sh);
                    i1 += B; i2 += B;
                    __stcs(&out[i1], v1);   // two independent STG.128 per step
                    __stcs(&out[i2], v2);
                }
                continue;
            }
        }
        // Tail / partial-chunk path
        fill_chunk(out, w, B, t, bh, gh, sh);
        if (w2 < total)
            fill_chunk(out, w2, B, t, bh, gh, sh);
    }
}

extern "C" void kernel_launch(void* const* d_in, const int* in_sizes, int n_in,
                              void* d_out, int out_size)
{
    const float* initial = (const float*)d_in[0];   // 4*B elements
    const float* beta    = (const float*)d_in[1];
    const float* gamma   = (const float*)d_in[2];
    const float* sigma   = (const float*)d_in[3];

    const int B = in_sizes[0] / 4;
    const int t = (B > 0) ? (out_size / (4 * B)) : 0;
    if (B <= 0 || t <= 0) return;

    const int nchunks = (t + CHUNK - 1) / CHUNK;
    const long long total = (long long)nchunks * B;

    // Phase 1: chain + checkpoints (chain-latency bound, ~6 us)
    seir_ckpt_kernel<<<(B + 127) / 128, 128>>>(initial, beta, gamma, sigma,
                                               (float4*)d_out, B, t);

    // Phase 2: persistent store engine (write-BW bound)
    long long want = (total + P2_BLOCK - 1) / P2_BLOCK;   // never exceed work
    int grid = (int)((want < P2_GRID) ? want : P2_GRID);
    seir_store_kernel<<<grid, P2_BLOCK>>>(beta, gamma, sigma,
                                          (float4*)d_out, B, t, total);
}

// round 9
// speedup vs baseline: 1.1051x; 1.0358x over previous
#include <cuda_runtime.h>
#include <cuda_bf16.h>

// SEIR Euler — FUSED single-kernel producer/consumer scheme.
//
// 536 MB of output stores at the measured ~6 TB/s write ceiling = 88.6 us
// floor. The two-kernel versions waste ~10 us of store-idle time during the
// serial phase-1 chain. Fuse: within each CTA, warp 0 runs the chain for 32
// regions and publishes 32-step checkpoints through SMEM flags; warps 1-7
// consume chunks as they appear and stream-store the 31 interior steps.
// All synchronization is intra-CTA (SMEM flags + threadfence_block) ->
// deadlock-free regardless of residency.

#define CHUNK      32
#define MAX_CHUNKS 32          // fused path supports t <= 1024
#define BPC        32          // regions per CTA (= producer warp lanes)
#define BLOCK      256

__device__ __forceinline__ float4 seir_step(float4 v, float bh, float gh, float sh)
{
    const float S = v.x, E = v.y, I = v.z, R = v.w;
    const float p = bh * S;
    float4 r;
    r.x = __fmaf_rn(-p, I, S);
    r.y = __fmaf_rn( p, I, __fmaf_rn(-sh, E, E));
    r.z = __fmaf_rn( sh, E, __fmaf_rn(-gh, I, I));
    r.w = __fmaf_rn( gh, I, R);
    return r;
}

__global__ void __launch_bounds__(BLOCK) seir_fused_kernel(
    const float* __restrict__ initial,
    const float* __restrict__ beta,
    const float* __restrict__ gamma,
    const float* __restrict__ sigma,
    float4* __restrict__ out,
    int B, int t)
{
    __shared__ float4   ckpt[MAX_CHUNKS][BPC];
    __shared__ unsigned flags[MAX_CHUNKS];

    const int g   = blockIdx.x;
    const int tid = threadIdx.x;
    const int nchunks = t / CHUNK;            // exact in fused path

    const float step = 0.5f;
    const float bh = beta[0]  * step;
    const float gh = gamma[0] * step;
    const float sh = sigma[0] * step;

    for (int i = tid; i < MAX_CHUNKS; i += BLOCK) flags[i] = 0u;
    __syncthreads();

    volatile unsigned* vflags = flags;

    if (tid < 32) {
        // ---- Producer warp: serial chain for 32 regions, publish checkpoints ----
        const int l = tid;
        const int b = g * BPC + l;
        float4 v = make_float4(initial[0 * B + b], initial[1 * B + b],
                               initial[2 * B + b], initial[3 * B + b]);
        for (int c = 0; c < nchunks; ++c) {
            ckpt[c][l] = v;
            out[(size_t)c * CHUNK * B + b] = v;      // checkpoint's own out slot
            __syncwarp();
            if (l == 0) { __threadfence_block(); vflags[c] = 1u; }
            if (c + 1 < nchunks) {
                #pragma unroll 8
                for (int j = 0; j < CHUNK; ++j)
                    v = seir_step(v, bh, gh, sh);
            }
        }
    } else {
        // ---- Consumer warps: fill 31 interior steps of each published chunk ----
        const int q = tid - 32;                 // 0..223 ; 224 % 32 == 0 keeps
        const int nitems = nchunks * BPC;       // warps chunk-aligned
        for (int i = q; i < nitems; i += (BLOCK - 32)) {
            const int c = i >> 5;
            const int l = i & 31;
            while (vflags[c] == 0u) { }
            __threadfence_block();
            float4 v = ckpt[c][l];
            const int b = g * BPC + l;
            size_t idx = (size_t)c * CHUNK * B + b;
            #pragma unroll
            for (int j = 1; j < CHUNK; ++j) {
                v = seir_step(v, bh, gh, sh);
                idx += B;
                __stcs(&out[idx], v);
            }
        }
    }
}

// ---- Fallback two-kernel path (round-6 known-good) for generic shapes ----
__global__ void __launch_bounds__(128) seir_ckpt_kernel(
    const float* __restrict__ initial, const float* __restrict__ beta,
    const float* __restrict__ gamma,   const float* __restrict__ sigma,
    float4* __restrict__ out, int B, int t)
{
    const int b = blockIdx.x * blockDim.x + threadIdx.x;
    if (b >= B) return;
    const float step = 0.5f;
    const float bh = beta[0]*step, gh = gamma[0]*step, sh = sigma[0]*step;
    float4 v = make_float4(initial[0*B+b], initial[1*B+b],
                           initial[2*B+b], initial[3*B+b]);
    out[b] = v;
    const int nchunks = (t + CHUNK - 1) / CHUNK;
    for (int c = 1; c < nchunks; ++c) {
        const int base = (c - 1) * CHUNK;
        const int steps = min(CHUNK, t - base);
        for (int j = 0; j < steps; ++j) v = seir_step(v, bh, gh, sh);
        if (c * CHUNK < t) out[(size_t)c * CHUNK * B + b] = v;
    }
}

__global__ void __launch_bounds__(256) seir_store_kernel(
    const float* __restrict__ beta, const float* __restrict__ gamma,
    const float* __restrict__ sigma, float4* __restrict__ out,
    int B, int t)
{
    const int tid = blockIdx.x * blockDim.x + threadIdx.x;
    const int c  = tid / B;
    const int bb = tid - c * B;
    const int n0 = c * CHUNK;
    if (n0 >= t || bb >= B) return;
    const float step = 0.5f;
    const float bh = beta[0]*step, gh = gamma[0]*step, sh = sigma[0]*step;
    size_t idx = (size_t)n0 * B + bb;
    float4 v = out[idx];
    const int nlast = min(n0 + CHUNK, t);
    for (int n = n0 + 1; n < nlast; ++n) {
        v = seir_step(v, bh, gh, sh);
        idx += B;
        __stcs(&out[idx], v);
    }
}

extern "C" void kernel_launch(void* const* d_in, const int* in_sizes, int n_in,
                              void* d_out, int out_size)
{
    const float* initial = (const float*)d_in[0];   // 4*B elements
    const float* beta    = (const float*)d_in[1];
    const float* gamma   = (const float*)d_in[2];
    const float* sigma   = (const float*)d_in[3];

    const int B = in_sizes[0] / 4;
    const int t = (B > 0) ? (out_size / (4 * B)) : 0;
    if (B <= 0 || t <= 0) return;

    if ((B % BPC) == 0 && (t % CHUNK) == 0 && (t / CHUNK) <= MAX_CHUNKS) {
        // Fused path: one launch, chain hidden under the store stream.
        seir_fused_kernel<<<B / BPC, BLOCK>>>(initial, beta, gamma, sigma,
                                              (float4*)d_out, B, t);
    } else {
        const int nchunks = (t + CHUNK - 1) / CHUNK;
        const long long total = (long long)nchunks * B;
        seir_ckpt_kernel<<<(B + 127) / 128, 128>>>(initial, beta, gamma, sigma,
                                                   (float4*)d_out, B, t);
        seir_store_kernel<<<(int)((total + 255) / 256), 256>>>(
            beta, gamma, sigma, (float4*)d_out, B, t);
    }
}

// round 10
// speedup vs baseline: 1.1645x; 1.0538x over previous
#include <cuda_runtime.h>
#include <cuda_bf16.h>

// SEIR Euler — fused producer/consumer, work-queue edition.
//
// Round-9 fused kernel won (92.8us) but ran stores at only 5.19 TB/s with
// DRAM just 63% busy -> store-supply limited. Fixes:
//  * all warps (incl. the producer once its chain is done) pull chunk work
//    from a shared-memory counter (warp-aggregated atomicAdd)
//  * each warp processes TWO chunks interleaved (2 independent STG.128
//    streams per chain step) -> ~2.3x stores in flight per SM.
// All synchronization intra-CTA (SMEM flags + counter) -> deadlock-free.

#define CHUNK      32
#define MAX_CHUNKS 32          // fused path supports t <= 1024
#define BPC        32          // regions per CTA (= producer warp lanes)
#define BLOCK      256

__device__ __forceinline__ float4 seir_step(float4 v, float bh, float gh, float sh)
{
    const float S = v.x, E = v.y, I = v.z, R = v.w;
    const float p = bh * S;
    float4 r;
    r.x = __fmaf_rn(-p, I, S);
    r.y = __fmaf_rn( p, I, __fmaf_rn(-sh, E, E));
    r.z = __fmaf_rn( sh, E, __fmaf_rn(-gh, I, I));
    r.w = __fmaf_rn( gh, I, R);
    return r;
}

__global__ void __launch_bounds__(BLOCK) seir_fused_kernel(
    const float* __restrict__ initial,
    const float* __restrict__ beta,
    const float* __restrict__ gamma,
    const float* __restrict__ sigma,
    float4* __restrict__ out,
    int B, int t)
{
    __shared__ float4   ckpt[MAX_CHUNKS][BPC];
    __shared__ unsigned flags[MAX_CHUNKS];
    __shared__ unsigned work_ctr;

    const int g    = blockIdx.x;
    const int tid  = threadIdx.x;
    const int wid  = tid >> 5;
    const int lane = tid & 31;
    const int nchunks = t / CHUNK;            // exact in fused path
    const int base_b  = g * BPC;

    const float step = 0.5f;
    const float bh = beta[0]  * step;
    const float gh = gamma[0] * step;
    const float sh = sigma[0] * step;

    for (int i = tid; i < MAX_CHUNKS; i += BLOCK) flags[i] = 0u;
    if (tid == 0) work_ctr = 0u;
    __syncthreads();

    volatile unsigned* vflags = flags;

    if (wid == 0) {
        // ---- Producer: serial chain for 32 regions, publish checkpoints ----
        const int b = base_b + lane;
        float4 v = make_float4(initial[0 * B + b], initial[1 * B + b],
                               initial[2 * B + b], initial[3 * B + b]);
        for (int c = 0; c < nchunks; ++c) {
            ckpt[c][lane] = v;
            __stcs(&out[(size_t)c * CHUNK * B + b], v);  // checkpoint out slot
            __syncwarp();
            if (lane == 0) { __threadfence_block(); vflags[c] = 1u; }
            if (c + 1 < nchunks) {
                #pragma unroll 8
                for (int j = 0; j < CHUNK; ++j)
                    v = seir_step(v, bh, gh, sh);
            }
        }
        // fall through: producer joins the consumer pool
    }

    // ---- Consumers (all warps): pull chunk pairs from the work queue ----
    for (;;) {
        unsigned base;
        if (lane == 0) base = atomicAdd(&work_ctr, 2u);
        base = __shfl_sync(0xFFFFFFFFu, base, 0);
        if (base >= (unsigned)nchunks) break;

        const int c0 = (int)base;
        const int c1 = c0 + 1;
        const bool has2 = (c1 < nchunks);

        while (vflags[c0] == 0u) { }
        if (has2) { while (vflags[c1] == 0u) { } }
        __threadfence_block();

        float4 v0 = ckpt[c0][lane];
        size_t i0 = (size_t)c0 * CHUNK * B + base_b + lane;

        if (has2) {
            float4 v1 = ckpt[c1][lane];
            size_t i1 = (size_t)c1 * CHUNK * B + base_b + lane;
            #pragma unroll
            for (int j = 1; j < CHUNK; ++j) {
                v0 = seir_step(v0, bh, gh, sh);
                v1 = seir_step(v1, bh, gh, sh);
                i0 += B; i1 += B;
                __stcs(&out[i0], v0);   // two independent streams per step
                __stcs(&out[i1], v1);
            }
        } else {
            #pragma unroll
            for (int j = 1; j < CHUNK; ++j) {
                v0 = seir_step(v0, bh, gh, sh);
                i0 += B;
                __stcs(&out[i0], v0);
            }
        }
    }
}

// ---- Fallback two-kernel path (known-good) for generic shapes ----
__global__ void __launch_bounds__(128) seir_ckpt_kernel(
    const float* __restrict__ initial, const float* __restrict__ beta,
    const float* __restrict__ gamma,   const float* __restrict__ sigma,
    float4* __restrict__ out, int B, int t)
{
    const int b = blockIdx.x * blockDim.x + threadIdx.x;
    if (b >= B) return;
    const float step = 0.5f;
    const float bh = beta[0]*step, gh = gamma[0]*step, sh = sigma[0]*step;
    float4 v = make_float4(initial[0*B+b], initial[1*B+b],
                           initial[2*B+b], initial[3*B+b]);
    out[b] = v;
    const int nchunks = (t + CHUNK - 1) / CHUNK;
    for (int c = 1; c < nchunks; ++c) {
        const int base = (c - 1) * CHUNK;
        const int steps = min(CHUNK, t - base);
        for (int j = 0; j < steps; ++j) v = seir_step(v, bh, gh, sh);
        if (c * CHUNK < t) out[(size_t)c * CHUNK * B + b] = v;
    }
}

__global__ void __launch_bounds__(256) seir_store_kernel(
    const float* __restrict__ beta, const float* __restrict__ gamma,
    const float* __restrict__ sigma, float4* __restrict__ out,
    int B, int t)
{
    const int tid = blockIdx.x * blockDim.x + threadIdx.x;
    const int c  = tid / B;
    const int bb = tid - c * B;
    const int n0 = c * CHUNK;
    if (n0 >= t || bb >= B) return;
    const float step = 0.5f;
    const float bh = beta[0]*step, gh = gamma[0]*step, sh = sigma[0]*step;
    size_t idx = (size_t)n0 * B + bb;
    float4 v = out[idx];
    const int nlast = min(n0 + CHUNK, t);
    for (int n = n0 + 1; n < nlast; ++n) {
        v = seir_step(v, bh, gh, sh);
        idx += B;
        __stcs(&out[idx], v);
    }
}

extern "C" void kernel_launch(void* const* d_in, const int* in_sizes, int n_in,
                              void* d_out, int out_size)
{
    const float* initial = (const float*)d_in[0];   // 4*B elements
    const float* beta    = (const float*)d_in[1];
    const float* gamma   = (const float*)d_in[2];
    const float* sigma   = (const float*)d_in[3];

    const int B = in_sizes[0] / 4;
    const int t = (B > 0) ? (out_size / (4 * B)) : 0;
    if (B <= 0 || t <= 0) return;

    if ((B % BPC) == 0 && (t % CHUNK) == 0 && (t / CHUNK) <= MAX_CHUNKS) {
        seir_fused_kernel<<<B / BPC, BLOCK>>>(initial, beta, gamma, sigma,
                                              (float4*)d_out, B, t);
    } else {
        const int nchunks = (t + CHUNK - 1) / CHUNK;
        const long long total = (long long)nchunks * B;
        seir_ckpt_kernel<<<(B + 127) / 128, 128>>>(initial, beta, gamma, sigma,
                                                   (float4*)d_out, B, t);
        seir_store_kernel<<<(int)((total + 255) / 256), 256>>>(
            beta, gamma, sigma, (float4*)d_out, B, t);
    }
}